// round 5
// baseline (speedup 1.0000x reference)
#include <cuda_runtime.h>
#include <cstdint>

#define BATCH  256
#define DIM    4096
#define BD     (BATCH * DIM)
#define NSTEPS 30
#define STAGES 3

// Stage word layout: A[256][36] then W[NT][36]  (pad 36: 36%32==4 -> conflict-free frags)
#define A_WORDS (256 * 36)
#define STAGE_WORDS_MAX (A_WORDS + 128 * 36)
#define SMEM_BYTES (STAGES * STAGE_WORDS_MAX * 4)

// ---------------- persistent device scratch ----------------
__device__ uint32_t gW0[(size_t)DIM * DIM];
__device__ uint32_t gW1[(size_t)DIM * DIM];
__device__ uint32_t gW2[(size_t)DIM * DIM];
__device__ uint32_t gW3[(size_t)DIM * DIM];
__device__ uint32_t gW4[(size_t)DIM * DIM];
__device__ float    g_sf[2][3][BD];      // fp32 state, double buffered
__device__ uint32_t g_st[2][3][BD];      // tf32-rounded state (MMA operand)
__device__ uint32_t g_s3t[BD];           // tf32 of data layer
__device__ float    g_top[BD];           // s3 @ W4^T (constant across steps)

__device__ __forceinline__ uint32_t f2tf32(float x) {
    uint32_t r;
    asm("cvt.rna.tf32.f32 %0, %1;" : "=r"(r) : "f"(x));
    return r;
}
__device__ __forceinline__ void cp16(uint32_t* sdst, const uint32_t* gsrc) {
    uint32_t sa = (uint32_t)__cvta_generic_to_shared(sdst);
    asm volatile("cp.async.cg.shared.global [%0], [%1], 16;\n" :: "r"(sa), "l"(gsrc));
}
__device__ __forceinline__ void cp_commit() { asm volatile("cp.async.commit_group;\n"); }
__device__ __forceinline__ void cp_wait1()  { asm volatile("cp.async.wait_group 1;\n"); }

__device__ __forceinline__ void mma8(float c[4], const uint32_t a[4], const uint32_t b[2]) {
    asm volatile(
        "mma.sync.aligned.m16n8k8.row.col.f32.tf32.tf32.f32 "
        "{%0,%1,%2,%3},{%4,%5,%6,%7},{%8,%9},{%0,%1,%2,%3};\n"
        : "+f"(c[0]), "+f"(c[1]), "+f"(c[2]), "+f"(c[3])
        : "r"(a[0]), "r"(a[1]), "r"(a[2]), "r"(a[3]), "r"(b[0]), "r"(b[1]));
}

// ---------------- fused GEMM(+update) block-unit ----------------
// C[256, NT] = A0[256,4096] @ W0p[NT,4096]^T  (+ tiles t>=128: A1 @ W1p^T)
// NT=128: 8 warps as 4x2, warp tile 64x64 (MI=4).
// NT=64 : 8 warps as 8x1, warp tile 32x64 (MI=2).
template <int NT, bool RAW>
__device__ __forceinline__ void gemm_unit(
    uint32_t* sm, int nTiles,
    const uint32_t* __restrict__ A0, const uint32_t* __restrict__ W0p,
    const uint32_t* __restrict__ A1, const uint32_t* __restrict__ W1p,
    int nBase,
    const float* __restrict__ oldS, float* __restrict__ newSf,
    uint32_t* __restrict__ newSt, const float* __restrict__ bias,
    const float* __restrict__ topP, float* __restrict__ rawOut)
{
    constexpr int MI  = (NT == 128) ? 4 : 2;        // m16 tiles per warp (M)
    constexpr int WTM = MI * 16;                    // warp M extent
    constexpr int STAGE_WORDS = A_WORDS + NT * 36;

    const int tid  = threadIdx.x;
    const int warp = tid >> 5;
    const int lane = tid & 31;
    const int lq   = lane >> 2;                     // 0..7
    const int lr   = lane & 3;                      // 0..3
    const int warpM = (NT == 128) ? (warp >> 1) : warp;  // 0..3 or 0..7
    const int warpN = (NT == 128) ? (warp & 1)  : 0;     // 0..1 or 0

    float acc[MI][8][4];                            // warp tile WTM x 64
    #pragma unroll
    for (int mi = 0; mi < MI; mi++)
        #pragma unroll
        for (int ni = 0; ni < 8; ni++)
            #pragma unroll
            for (int f = 0; f < 4; f++) acc[mi][ni][f] = 0.0f;

    // ---- async load of one K-tile (32 tf32 cols) into stage s ----
    auto load_tile = [&](int s, int t) {
        const uint32_t* A = (t < 128) ? A0 : A1;
        const uint32_t* W = (t < 128) ? W0p : W1p;
        const int kOff = (t & 127) * 32;
        uint32_t* smA = sm + s * STAGE_WORDS;
        uint32_t* smW = smA + A_WORDS;
        #pragma unroll
        for (int j = 0; j < 8; j++) {               // A: 2048 float4
            int f = tid + 256 * j;
            int row = f >> 3, c = (f & 7) * 4;
            cp16(smA + row * 36 + c, A + (size_t)row * DIM + kOff + c);
        }
        #pragma unroll
        for (int j = 0; j < NT / 32; j++) {         // W: NT*8 float4
            int f = tid + 256 * j;
            int row = f >> 3, c = (f & 7) * 4;
            cp16(smW + row * 36 + c, W + (size_t)row * DIM + kOff + c);
        }
    };

    int ld = 0;
    #pragma unroll
    for (int s = 0; s < STAGES - 1; s++) { load_tile(s, ld); cp_commit(); ld++; }

    uint32_t afr[2][MI][4];                         // double-buffered fragments
    uint32_t bfr[2][8][2];

    auto load_frag = [&](const uint32_t* smA, const uint32_t* smW, int kk, int pb) {
        #pragma unroll
        for (int mi = 0; mi < MI; mi++) {
            int r = warpM * WTM + mi * 16 + lq;
            afr[pb][mi][0] = smA[(r    ) * 36 + kk     + lr];
            afr[pb][mi][1] = smA[(r + 8) * 36 + kk     + lr];
            afr[pb][mi][2] = smA[(r    ) * 36 + kk + 4 + lr];
            afr[pb][mi][3] = smA[(r + 8) * 36 + kk + 4 + lr];
        }
        #pragma unroll
        for (int ni = 0; ni < 8; ni++) {
            int c = warpN * 64 + ni * 8 + lq;
            bfr[pb][ni][0] = smW[c * 36 + kk     + lr];
            bfr[pb][ni][1] = smW[c * 36 + kk + 4 + lr];
        }
    };

    for (int t = 0; t < nTiles; t++) {
        cp_wait1();
        __syncthreads();
        const uint32_t* smA = sm + (t % STAGES) * STAGE_WORDS;
        const uint32_t* smW = smA + A_WORDS;

        if (ld < nTiles) { load_tile(ld % STAGES, ld); ld++; }
        cp_commit();

        load_frag(smA, smW, 0, 0);
        #pragma unroll
        for (int ks = 0; ks < 4; ks++) {
            const int pb = ks & 1;
            if (ks < 3) load_frag(smA, smW, (ks + 1) * 8, pb ^ 1);
            #pragma unroll
            for (int mi = 0; mi < MI; mi++)
                #pragma unroll
                for (int ni = 0; ni < 8; ni++)
                    mma8(acc[mi][ni], afr[pb][mi], bfr[pb][ni]);
        }
        __syncthreads();
    }

    // ---- fused epilogue (each output element owned by this block) ----
    #pragma unroll
    for (int mi = 0; mi < MI; mi++) {
        #pragma unroll
        for (int ni = 0; ni < 8; ni++) {
            int r0 = warpM * WTM + mi * 16 + lq;
            int c0 = nBase + warpN * 64 + ni * 8 + 2 * lr;
            #pragma unroll
            for (int h = 0; h < 2; h++) {
                int r = r0 + 8 * h;
                #pragma unroll
                for (int g = 0; g < 2; g++) {
                    int c = c0 + g;
                    float y = acc[mi][ni][2 * h + g];
                    size_t idx = (size_t)r * DIM + c;
                    if (RAW) {
                        rawOut[idx] = y;
                    } else {
                        y += bias[c];
                        if (topP) y += topP[idx];
                        float ns = 0.5f * oldS[idx] + 0.5f * y;
                        ns = fminf(fmaxf(ns, 0.0f), 1.0f);
                        newSf[idx] = ns;
                        newSt[idx] = f2tf32(ns);
                    }
                }
            }
        }
    }
}

// -------- one relaxation step: 128 equal-work blocks, one wave --------
__global__ void __launch_bounds__(256, 1) step_kernel(
    int p, const float* __restrict__ b0, const float* __restrict__ b2,
    const float* __restrict__ b4)
{
    extern __shared__ uint32_t sm[];
    const int bid = blockIdx.x;
    const int q = p ^ 1;
    if (bid < 32) {                 // s0' <- clip(.5 s0 + .5 (s1 @ W0^T + b0))
        const int nB = bid * 128;
        gemm_unit<128, false>(sm, 128, g_st[p][1], gW0 + (size_t)nB * DIM,
                              g_st[p][1], gW0 + (size_t)nB * DIM, nB,
                              g_sf[p][0], g_sf[q][0], g_st[q][0], b0, nullptr, nullptr);
    } else if (bid < 96) {          // s1' <- clip(.5 s1 + .5 (s2 @ W2^T + s0 @ W1^T + b2))
        const int nB = (bid - 32) * 64;
        gemm_unit<64, false>(sm, 256, g_st[p][2], gW2 + (size_t)nB * DIM,
                             g_st[p][0], gW1 + (size_t)nB * DIM, nB,
                             g_sf[p][1], g_sf[q][1], g_st[q][1], b2, nullptr, nullptr);
    } else {                        // s2' <- clip(.5 s2 + .5 (s1 @ W3^T + top + b4))
        const int nB = (bid - 96) * 128;
        gemm_unit<128, false>(sm, 128, g_st[p][1], gW3 + (size_t)nB * DIM,
                              g_st[p][1], gW3 + (size_t)nB * DIM, nB,
                              g_sf[p][2], g_sf[q][2], g_st[q][2], b4, g_top, nullptr);
    }
}

__global__ void __launch_bounds__(256, 1) top_kernel()
{
    extern __shared__ uint32_t sm[];
    const int nB = blockIdx.x * 128;
    gemm_unit<128, true>(sm, 128, g_s3t, gW4 + (size_t)nB * DIM,
                         g_s3t, gW4 + (size_t)nB * DIM, nB,
                         nullptr, nullptr, nullptr, nullptr, nullptr, g_top);
}

// -------- setup / teardown --------
__global__ void wconv_kernel(const float* __restrict__ w0, const float* __restrict__ w1,
                             const float* __restrict__ w2, const float* __restrict__ w3,
                             const float* __restrict__ w4)
{
    const float* src;
    uint32_t* dst;
    switch (blockIdx.y) {
        case 0: src = w0; dst = gW0; break;
        case 1: src = w1; dst = gW1; break;
        case 2: src = w2; dst = gW2; break;
        case 3: src = w3; dst = gW3; break;
        default: src = w4; dst = gW4; break;
    }
    size_t i = ((size_t)blockIdx.x * blockDim.x + threadIdx.x) * 4;
    float4 v = *(const float4*)(src + i);
    uint4 o;
    o.x = f2tf32(v.x); o.y = f2tf32(v.y); o.z = f2tf32(v.z); o.w = f2tf32(v.w);
    *(uint4*)(dst + i) = o;
}

__global__ void init_kernel(const float* __restrict__ s0, const float* __restrict__ s1,
                            const float* __restrict__ s2, const float* __restrict__ s3)
{
    int i = blockIdx.x * blockDim.x + threadIdx.x;
    float v0 = s0[i], v1 = s1[i], v2 = s2[i];
    g_sf[0][0][i] = v0; g_st[0][0][i] = f2tf32(v0);
    g_sf[0][1][i] = v1; g_st[0][1][i] = f2tf32(v1);
    g_sf[0][2][i] = v2; g_st[0][2][i] = f2tf32(v2);
    g_s3t[i] = f2tf32(s3[i]);
}

__global__ void out_kernel(float* __restrict__ out)
{
    int i = blockIdx.x * blockDim.x + threadIdx.x;
    out[i]          = g_sf[0][0][i];
    out[BD + i]     = g_sf[0][1][i];
    out[2 * BD + i] = g_sf[0][2][i];
}

extern "C" void kernel_launch(void* const* d_in, const int* in_sizes, int n_in,
                              void* d_out, int out_size)
{
    const float* s0 = (const float*)d_in[0];
    const float* s1 = (const float*)d_in[1];
    const float* s2 = (const float*)d_in[2];
    const float* s3 = (const float*)d_in[3];
    const float* W0 = (const float*)d_in[4];
    const float* b0 = (const float*)d_in[5];
    const float* W1 = (const float*)d_in[6];
    const float* W2 = (const float*)d_in[7];
    const float* b2 = (const float*)d_in[8];
    const float* W3 = (const float*)d_in[9];
    const float* W4 = (const float*)d_in[10];
    const float* b4 = (const float*)d_in[11];

    static_assert(SMEM_BYTES <= 227 * 1024, "smem budget");
    cudaFuncSetAttribute(step_kernel, cudaFuncAttributeMaxDynamicSharedMemorySize, SMEM_BYTES);
    cudaFuncSetAttribute(top_kernel,  cudaFuncAttributeMaxDynamicSharedMemorySize, SMEM_BYTES);

    wconv_kernel<<<dim3(DIM * DIM / 4 / 256, 5), 256>>>(W0, W1, W2, W3, W4);
    init_kernel<<<BD / 256, 256>>>(s0, s1, s2, s3);

    top_kernel<<<32, 256, SMEM_BYTES>>>();

    for (int t = 0; t < NSTEPS; t++)
        step_kernel<<<128, 256, SMEM_BYTES>>>(t & 1, b0, b2, b4);

    out_kernel<<<BD / 256, 256>>>((float*)d_out);
}

// round 6
// speedup vs baseline: 1.0553x; 1.0553x over previous
#include <cuda_runtime.h>
#include <cstdint>

#define BATCH  256
#define DIM    4096
#define BD     (BATCH * DIM)
#define NSTEPS 30

// Per-half stage: A[128][36] + W[NT][36] words. 2 halves x 3 stages.
#define HALF_STAGE_MAX ((128 + 128) * 36)
#define SMEM_BYTES (2 * 3 * HALF_STAGE_MAX * 4)   // 221184 B

// ---------------- persistent device scratch ----------------
__device__ uint32_t gW0[(size_t)DIM * DIM];
__device__ uint32_t gW1[(size_t)DIM * DIM];
__device__ uint32_t gW2[(size_t)DIM * DIM];
__device__ uint32_t gW3[(size_t)DIM * DIM];
__device__ uint32_t gW4[(size_t)DIM * DIM];
__device__ float    g_sf[2][3][BD];      // fp32 state, double buffered
__device__ uint32_t g_st[2][3][BD];      // tf32-rounded state (MMA operand)
__device__ uint32_t g_s3t[BD];           // tf32 of data layer
__device__ float    g_top[BD];           // s3 @ W4^T (constant across steps)

__device__ __forceinline__ uint32_t f2tf32(float x) {
    uint32_t r;
    asm("cvt.rna.tf32.f32 %0, %1;" : "=r"(r) : "f"(x));
    return r;
}
__device__ __forceinline__ void cp16(uint32_t* sdst, const uint32_t* gsrc) {
    uint32_t sa = (uint32_t)__cvta_generic_to_shared(sdst);
    asm volatile("cp.async.cg.shared.global [%0], [%1], 16;\n" :: "r"(sa), "l"(gsrc));
}
__device__ __forceinline__ void cp_commit() { asm volatile("cp.async.commit_group;\n"); }
__device__ __forceinline__ void cp_wait1()  { asm volatile("cp.async.wait_group 1;\n"); }
__device__ __forceinline__ void hbar(int id) {
    asm volatile("bar.sync %0, %1;" :: "r"(id), "r"(128) : "memory");
}
__device__ __forceinline__ void ldsm4(uint32_t r[4], uint32_t saddr) {
    asm volatile("ldmatrix.sync.aligned.m8n8.x4.shared.b16 {%0,%1,%2,%3}, [%4];"
        : "=r"(r[0]), "=r"(r[1]), "=r"(r[2]), "=r"(r[3]) : "r"(saddr));
}
__device__ __forceinline__ void ldsm2(uint32_t r[2], uint32_t saddr) {
    asm volatile("ldmatrix.sync.aligned.m8n8.x2.shared.b16 {%0,%1}, [%2];"
        : "=r"(r[0]), "=r"(r[1]) : "r"(saddr));
}
__device__ __forceinline__ void mma8(float c[4], const uint32_t a[4], const uint32_t b[2]) {
    asm volatile(
        "mma.sync.aligned.m16n8k8.row.col.f32.tf32.tf32.f32 "
        "{%0,%1,%2,%3},{%4,%5,%6,%7},{%8,%9},{%0,%1,%2,%3};\n"
        : "+f"(c[0]), "+f"(c[1]), "+f"(c[2]), "+f"(c[3])
        : "r"(a[0]), "r"(a[1]), "r"(a[2]), "r"(a[3]), "r"(b[0]), "r"(b[1]));
}

// ---------------- fused GEMM(+update) block-unit, split into 2 halves ----------------
// C[256, NT] = A0[256,4096] @ W0p[NT,4096]^T  (+ tiles t>=128: A1 @ W1p^T)
// Half h owns rows [h*128, h*128+128): 4 warps.
// NT=128: warp tile 64x64 (MI=4, 2x2). NT=64: warp tile 32x64 (MI=2, 4x1).
template <int NT, bool RAW>
__device__ __forceinline__ void gemm_unit(
    uint32_t* sm, int nTiles,
    const uint32_t* __restrict__ A0, const uint32_t* __restrict__ W0p,
    const uint32_t* __restrict__ A1, const uint32_t* __restrict__ W1p,
    int nBase,
    const float* __restrict__ oldS, float* __restrict__ newSf,
    uint32_t* __restrict__ newSt, const float* __restrict__ bias,
    const float* __restrict__ topP, float* __restrict__ rawOut)
{
    constexpr int MI  = (NT == 128) ? 4 : 2;        // m16 tiles per warp (M)
    constexpr int WTM = MI * 16;                    // warp M extent
    constexpr int HALF_STAGE = (128 + NT) * 36;     // words per stage per half

    const int tid   = threadIdx.x;
    const int warp  = tid >> 5;
    const int lane  = tid & 31;
    const int half  = warp >> 2;                    // 0 or 1
    const int hwarp = warp & 3;                     // warp within half
    const int htid  = tid & 127;
    const int lq    = lane >> 2;
    const int lr    = lane & 3;
    const int warpM = (NT == 128) ? (hwarp >> 1) : hwarp;   // 0..1 or 0..3
    const int warpN = (NT == 128) ? (hwarp & 1)  : 0;       // 0..1 or 0

    uint32_t* smH = sm + half * (3 * HALF_STAGE);
    const uint32_t smH_b = (uint32_t)__cvta_generic_to_shared(smH);

    // ldmatrix lane address components (b32 tiles, 36-word pitch = 144 B)
    const int t4      = lane >> 3;
    const int rin     = lane & 7;
    const int aRowOff = rin + 8 * (t4 & 1);         // row within 16-row group
    const int aColB   = 4 * (t4 >> 1) * 4;          // col offset bytes (0 or 16)
    const int bRin    = lane & 7;
    const int bColB   = 4 * ((lane >> 3) & 1) * 4;  // 0 or 16 (lanes 16-31 ignored by x2)

    int aRowByte[MI];
    #pragma unroll
    for (int mi = 0; mi < MI; mi++)
        aRowByte[mi] = (warpM * WTM + mi * 16 + aRowOff) * 144 + aColB;
    int bRowByte[8];
    #pragma unroll
    for (int ni = 0; ni < 8; ni++)
        bRowByte[ni] = (128 + warpN * 64 + ni * 8 + bRin) * 144 + bColB;  // +128 rows = W region

    float acc[MI][8][4];
    #pragma unroll
    for (int mi = 0; mi < MI; mi++)
        #pragma unroll
        for (int ni = 0; ni < 8; ni++)
            #pragma unroll
            for (int f = 0; f < 4; f++) acc[mi][ni][f] = 0.0f;

    // ---- async load of one K-tile (32 tf32 cols) into this half's stage s ----
    auto load_tile = [&](int s, int t) {
        const uint32_t* A = (t < 128) ? A0 : A1;
        const uint32_t* W = (t < 128) ? W0p : W1p;
        const int kOff = (t & 127) * 32;
        uint32_t* smA = smH + s * HALF_STAGE;
        uint32_t* smW = smA + 128 * 36;
        #pragma unroll
        for (int j = 0; j < 8; j++) {               // A: 128 rows x 8 float4
            int f = htid + 128 * j;
            int row = f >> 3, c = (f & 7) * 4;
            cp16(smA + row * 36 + c, A + (size_t)(half * 128 + row) * DIM + kOff + c);
        }
        #pragma unroll
        for (int j = 0; j < NT / 16; j++) {         // W: NT rows x 8 float4
            int f = htid + 128 * j;
            int row = f >> 3, c = (f & 7) * 4;
            cp16(smW + row * 36 + c, W + (size_t)row * DIM + kOff + c);
        }
    };

    load_tile(0, 0); cp_commit();
    load_tile(1, 1); cp_commit();

    uint32_t afr[MI][4];
    uint32_t bfr[8][2];

    for (int t = 0; t < nTiles; t++) {
        cp_wait1();                                  // tile t's group done (per warp)
        hbar(half + 1);                              // half-wide: tile t visible, compute t-1 done
        if (t + 2 < nTiles) load_tile((t + 2) % 3, t + 2);
        cp_commit();

        const uint32_t stB = smH_b + (uint32_t)((t % 3) * HALF_STAGE * 4);
        #pragma unroll
        for (int ks = 0; ks < 4; ks++) {
            const int kkB = ks * 8 * 4;
            #pragma unroll
            for (int mi = 0; mi < MI; mi++)
                ldsm4(afr[mi], stB + aRowByte[mi] + kkB);
            #pragma unroll
            for (int ni = 0; ni < 8; ni++)
                ldsm2(bfr[ni], stB + bRowByte[ni] + kkB);
            #pragma unroll
            for (int mi = 0; mi < MI; mi++)
                #pragma unroll
                for (int ni = 0; ni < 8; ni++)
                    mma8(acc[mi][ni], afr[mi], bfr[ni]);
        }
    }

    // ---- fused epilogue (each output element owned by this block) ----
    #pragma unroll
    for (int mi = 0; mi < MI; mi++) {
        #pragma unroll
        for (int ni = 0; ni < 8; ni++) {
            int r0 = half * 128 + warpM * WTM + mi * 16 + lq;
            int c0 = nBase + warpN * 64 + ni * 8 + 2 * lr;
            #pragma unroll
            for (int h = 0; h < 2; h++) {
                int r = r0 + 8 * h;
                #pragma unroll
                for (int g = 0; g < 2; g++) {
                    int c = c0 + g;
                    float y = acc[mi][ni][2 * h + g];
                    size_t idx = (size_t)r * DIM + c;
                    if (RAW) {
                        rawOut[idx] = y;
                    } else {
                        y += bias[c];
                        if (topP) y += topP[idx];
                        float ns = 0.5f * oldS[idx] + 0.5f * y;
                        ns = fminf(fmaxf(ns, 0.0f), 1.0f);
                        newSf[idx] = ns;
                        newSt[idx] = f2tf32(ns);
                    }
                }
            }
        }
    }
}

// -------- one relaxation step: 128 equal-work blocks, one wave --------
__global__ void __launch_bounds__(256, 1) step_kernel(
    int p, const float* __restrict__ b0, const float* __restrict__ b2,
    const float* __restrict__ b4)
{
    extern __shared__ uint32_t sm[];
    const int bid = blockIdx.x;
    const int q = p ^ 1;
    if (bid < 32) {                 // s0' <- clip(.5 s0 + .5 (s1 @ W0^T + b0))
        const int nB = bid * 128;
        gemm_unit<128, false>(sm, 128, g_st[p][1], gW0 + (size_t)nB * DIM,
                              g_st[p][1], gW0 + (size_t)nB * DIM, nB,
                              g_sf[p][0], g_sf[q][0], g_st[q][0], b0, nullptr, nullptr);
    } else if (bid < 96) {          // s1' <- clip(.5 s1 + .5 (s2 @ W2^T + s0 @ W1^T + b2))
        const int nB = (bid - 32) * 64;
        gemm_unit<64, false>(sm, 256, g_st[p][2], gW2 + (size_t)nB * DIM,
                             g_st[p][0], gW1 + (size_t)nB * DIM, nB,
                             g_sf[p][1], g_sf[q][1], g_st[q][1], b2, nullptr, nullptr);
    } else {                        // s2' <- clip(.5 s2 + .5 (s1 @ W3^T + top + b4))
        const int nB = (bid - 96) * 128;
        gemm_unit<128, false>(sm, 128, g_st[p][1], gW3 + (size_t)nB * DIM,
                              g_st[p][1], gW3 + (size_t)nB * DIM, nB,
                              g_sf[p][2], g_sf[q][2], g_st[q][2], b4, g_top, nullptr);
    }
}

__global__ void __launch_bounds__(256, 1) top_kernel()
{
    extern __shared__ uint32_t sm[];
    const int nB = blockIdx.x * 128;
    gemm_unit<128, true>(sm, 128, g_s3t, gW4 + (size_t)nB * DIM,
                         g_s3t, gW4 + (size_t)nB * DIM, nB,
                         nullptr, nullptr, nullptr, nullptr, nullptr, g_top);
}

// -------- setup / teardown --------
__global__ void wconv_kernel(const float* __restrict__ w0, const float* __restrict__ w1,
                             const float* __restrict__ w2, const float* __restrict__ w3,
                             const float* __restrict__ w4)
{
    const float* src;
    uint32_t* dst;
    switch (blockIdx.y) {
        case 0: src = w0; dst = gW0; break;
        case 1: src = w1; dst = gW1; break;
        case 2: src = w2; dst = gW2; break;
        case 3: src = w3; dst = gW3; break;
        default: src = w4; dst = gW4; break;
    }
    size_t i = ((size_t)blockIdx.x * blockDim.x + threadIdx.x) * 4;
    float4 v = *(const float4*)(src + i);
    uint4 o;
    o.x = f2tf32(v.x); o.y = f2tf32(v.y); o.z = f2tf32(v.z); o.w = f2tf32(v.w);
    *(uint4*)(dst + i) = o;
}

__global__ void init_kernel(const float* __restrict__ s0, const float* __restrict__ s1,
                            const float* __restrict__ s2, const float* __restrict__ s3)
{
    int i = blockIdx.x * blockDim.x + threadIdx.x;
    float v0 = s0[i], v1 = s1[i], v2 = s2[i];
    g_sf[0][0][i] = v0; g_st[0][0][i] = f2tf32(v0);
    g_sf[0][1][i] = v1; g_st[0][1][i] = f2tf32(v1);
    g_sf[0][2][i] = v2; g_st[0][2][i] = f2tf32(v2);
    g_s3t[i] = f2tf32(s3[i]);
}

__global__ void out_kernel(float* __restrict__ out)
{
    int i = blockIdx.x * blockDim.x + threadIdx.x;
    out[i]          = g_sf[0][0][i];
    out[BD + i]     = g_sf[0][1][i];
    out[2 * BD + i] = g_sf[0][2][i];
}

extern "C" void kernel_launch(void* const* d_in, const int* in_sizes, int n_in,
                              void* d_out, int out_size)
{
    const float* s0 = (const float*)d_in[0];
    const float* s1 = (const float*)d_in[1];
    const float* s2 = (const float*)d_in[2];
    const float* s3 = (const float*)d_in[3];
    const float* W0 = (const float*)d_in[4];
    const float* b0 = (const float*)d_in[5];
    const float* W1 = (const float*)d_in[6];
    const float* W2 = (const float*)d_in[7];
    const float* b2 = (const float*)d_in[8];
    const float* W3 = (const float*)d_in[9];
    const float* W4 = (const float*)d_in[10];
    const float* b4 = (const float*)d_in[11];

    static_assert(SMEM_BYTES <= 227 * 1024, "smem budget");
    cudaFuncSetAttribute(step_kernel, cudaFuncAttributeMaxDynamicSharedMemorySize, SMEM_BYTES);
    cudaFuncSetAttribute(top_kernel,  cudaFuncAttributeMaxDynamicSharedMemorySize, SMEM_BYTES);

    wconv_kernel<<<dim3(DIM * DIM / 4 / 256, 5), 256>>>(W0, W1, W2, W3, W4);
    init_kernel<<<BD / 256, 256>>>(s0, s1, s2, s3);

    top_kernel<<<32, 256, SMEM_BYTES>>>();

    for (int t = 0; t < NSTEPS; t++)
        step_kernel<<<128, 256, SMEM_BYTES>>>(t & 1, b0, b2, b4);

    out_kernel<<<BD / 256, 256>>>((float*)d_out);
}

// round 7
// speedup vs baseline: 2.6416x; 2.5032x over previous
#include <cuda_runtime.h>
#include <cuda_fp16.h>
#include <cstdint>

#define BATCH  256
#define DIM    4096
#define BD     (BATCH * DIM)
#define NSTEPS 30

// Half-block stage: (128 A rows + NT W rows) x 128 bytes (64 f16 k-values)
#define HSB_MAX (256 * 128)
#define SMEM_BYTES (2 * 3 * HSB_MAX)     // 196608 B

// ---------------- persistent device scratch ----------------
__device__ __half gW0[(size_t)DIM * DIM];
__device__ __half gW1[(size_t)DIM * DIM];
__device__ __half gW2[(size_t)DIM * DIM];
__device__ __half gW3[(size_t)DIM * DIM];
__device__ __half gW4[(size_t)DIM * DIM];
__device__ float  g_sf[2][3][BD];        // fp32 state, double buffered
__device__ __half g_sh[2][3][BD];        // f16 state copy (MMA operand)
__device__ __half g_s3h[BD];             // f16 of data layer
__device__ float  g_top[BD];             // s3 @ W4^T (constant across steps)

__device__ __forceinline__ void cp16(uint32_t sdst, const void* gsrc) {
    asm volatile("cp.async.cg.shared.global [%0], [%1], 16;\n" :: "r"(sdst), "l"(gsrc));
}
__device__ __forceinline__ void cp_commit() { asm volatile("cp.async.commit_group;\n"); }
__device__ __forceinline__ void cp_wait1()  { asm volatile("cp.async.wait_group 1;\n"); }
__device__ __forceinline__ void hbar(int id) {
    asm volatile("bar.sync %0, %1;" :: "r"(id), "r"(256) : "memory");
}
__device__ __forceinline__ void ldsm4(uint32_t r[4], uint32_t saddr) {
    asm volatile("ldmatrix.sync.aligned.m8n8.x4.shared.b16 {%0,%1,%2,%3}, [%4];"
        : "=r"(r[0]), "=r"(r[1]), "=r"(r[2]), "=r"(r[3]) : "r"(saddr));
}
__device__ __forceinline__ void mma16(float c[4], const uint32_t a[4], const uint32_t b[2]) {
    asm volatile(
        "mma.sync.aligned.m16n8k16.row.col.f32.f16.f16.f32 "
        "{%0,%1,%2,%3},{%4,%5,%6,%7},{%8,%9},{%0,%1,%2,%3};\n"
        : "+f"(c[0]), "+f"(c[1]), "+f"(c[2]), "+f"(c[3])
        : "r"(a[0]), "r"(a[1]), "r"(a[2]), "r"(a[3]), "r"(b[0]), "r"(b[1]));
}

// ---------------- fused GEMM(+update) block-unit, 2 independent halves ----------------
// C[256, NT] = A0[256,4096] @ W0p[NT,4096]^T  (+ tiles t>=64: A1 @ W1p^T)
// 512 threads = 2 halves x 8 warps. Half h owns rows [h*128, h*128+128).
// Warp tile 32 x (NT/2): warpM = hwarp>>1 (0..3), warpN = hwarp&1.
template <int NT, bool RAW>
__device__ __forceinline__ void gemm_unit(
    char* dsm, int nTiles,
    const __half* __restrict__ A0, const __half* __restrict__ W0p,
    const __half* __restrict__ A1, const __half* __restrict__ W1p,
    int nBase,
    const float* __restrict__ oldS, float* __restrict__ newSf,
    __half* __restrict__ newSh, const float* __restrict__ bias,
    const float* __restrict__ topP, float* __restrict__ rawOut)
{
    constexpr int NI  = NT / 16;                 // n8 tiles per warp (8 or 4)
    constexpr int HSB = (128 + NT) * 128;        // stage bytes per half

    const int tid   = threadIdx.x;
    const int warp  = tid >> 5;
    const int lane  = tid & 31;
    const int half  = warp >> 3;                 // 0 or 1
    const int hwarp = warp & 7;
    const int htid  = tid & 255;
    const int lq    = lane >> 2;
    const int lr    = lane & 3;
    const int warpM = hwarp >> 1;                // 0..3 (32-row tiles)
    const int warpN = hwarp & 1;

    const uint32_t smH_b = (uint32_t)__cvta_generic_to_shared(dsm) + half * (3 * HSB);
    const int msk = lane & 7;                    // swizzle mask (row&7 for all frag rows)

    // ldmatrix row-base byte offsets (swizzle chunk added per ks)
    const int aKh = lane >> 4;                   // k-half select for A
    const int bKh = (lane >> 3) & 1;             // k-half select for B
    int aByte[2];
    #pragma unroll
    for (int mi = 0; mi < 2; mi++) {
        int row = warpM * 32 + mi * 16 + (lane & 7) + 8 * ((lane >> 3) & 1);
        aByte[mi] = row * 128;
    }
    int bByte[NI / 2];
    #pragma unroll
    for (int j = 0; j < NI / 2; j++) {
        int row = 128 + warpN * (NI * 8) + j * 16 + (lane & 7) + 8 * (lane >> 4);
        bByte[j] = row * 128;
    }

    float acc[2][NI][4];
    #pragma unroll
    for (int mi = 0; mi < 2; mi++)
        #pragma unroll
        for (int ni = 0; ni < NI; ni++)
            #pragma unroll
            for (int f = 0; f < 4; f++) acc[mi][ni][f] = 0.0f;

    // ---- async load of one K-tile (64 f16 cols) into this half's stage s ----
    auto load_tile = [&](int s, int t) {
        const __half* A = (t < 64) ? A0 : A1;
        const __half* W = (t < 64) ? W0p : W1p;
        const int kOff = (t & 63) * 64;
        const uint32_t stA = smH_b + s * HSB;
        #pragma unroll
        for (int j = 0; j < 4; j++) {            // A: 128 rows x 8 chunks
            int f = htid + 256 * j;
            int row = f >> 3, c = f & 7;
            cp16(stA + row * 128 + ((c ^ (row & 7)) << 4),
                 A + (size_t)(half * 128 + row) * DIM + kOff + c * 8);
        }
        #pragma unroll
        for (int j = 0; j < NT / 32; j++) {      // W: NT rows x 8 chunks
            int f = htid + 256 * j;
            int row = f >> 3, c = f & 7;
            cp16(stA + 16384 + row * 128 + ((c ^ (row & 7)) << 4),
                 W + (size_t)row * DIM + kOff + c * 8);
        }
    };

    load_tile(0, 0); cp_commit();
    load_tile(1, 1); cp_commit();

    for (int t = 0; t < nTiles; t++) {
        cp_wait1();
        hbar(half + 1);
        if (t + 2 < nTiles) load_tile((t + 2) % 3, t + 2);
        cp_commit();

        const uint32_t stB = smH_b + (uint32_t)((t % 3) * HSB);
        #pragma unroll
        for (int ks = 0; ks < 4; ks++) {
            uint32_t afr[2][4];
            #pragma unroll
            for (int mi = 0; mi < 2; mi++)
                ldsm4(afr[mi], stB + aByte[mi] + ((((2 * ks + aKh) ^ msk)) << 4));
            uint32_t bfr[NI / 2][4];
            #pragma unroll
            for (int j = 0; j < NI / 2; j++)
                ldsm4(bfr[j], stB + bByte[j] + ((((2 * ks + bKh) ^ msk)) << 4));
            #pragma unroll
            for (int mi = 0; mi < 2; mi++)
                #pragma unroll
                for (int ni = 0; ni < NI; ni++)
                    mma16(acc[mi][ni], afr[mi], &bfr[ni >> 1][(ni & 1) * 2]);
        }
    }

    // ---- fused epilogue (each output element owned by this block) ----
    #pragma unroll
    for (int mi = 0; mi < 2; mi++) {
        #pragma unroll
        for (int ni = 0; ni < NI; ni++) {
            int r0 = half * 128 + warpM * 32 + mi * 16 + lq;
            int c0 = nBase + warpN * (NI * 8) + ni * 8 + 2 * lr;
            #pragma unroll
            for (int h = 0; h < 2; h++) {
                int r = r0 + 8 * h;
                #pragma unroll
                for (int g = 0; g < 2; g++) {
                    int c = c0 + g;
                    float y = acc[mi][ni][2 * h + g];
                    size_t idx = (size_t)r * DIM + c;
                    if (RAW) {
                        rawOut[idx] = y;
                    } else {
                        y += bias[c];
                        if (topP) y += topP[idx];
                        float ns = 0.5f * oldS[idx] + 0.5f * y;
                        ns = fminf(fmaxf(ns, 0.0f), 1.0f);
                        newSf[idx] = ns;
                        newSh[idx] = __float2half_rn(ns);
                    }
                }
            }
        }
    }
}

// -------- one relaxation step: 128 equal-work blocks, one wave --------
__global__ void __launch_bounds__(512, 1) step_kernel(
    int p, const float* __restrict__ b0, const float* __restrict__ b2,
    const float* __restrict__ b4)
{
    extern __shared__ char dsm[];
    const int bid = blockIdx.x;
    const int q = p ^ 1;
    if (bid < 32) {                 // s0' <- clip(.5 s0 + .5 (s1 @ W0^T + b0))
        const int nB = bid * 128;
        gemm_unit<128, false>(dsm, 64, g_sh[p][1], gW0 + (size_t)nB * DIM,
                              g_sh[p][1], gW0 + (size_t)nB * DIM, nB,
                              g_sf[p][0], g_sf[q][0], g_sh[q][0], b0, nullptr, nullptr);
    } else if (bid < 96) {          // s1' <- clip(.5 s1 + .5 (s2 @ W2^T + s0 @ W1^T + b2))
        const int nB = (bid - 32) * 64;
        gemm_unit<64, false>(dsm, 128, g_sh[p][2], gW2 + (size_t)nB * DIM,
                             g_sh[p][0], gW1 + (size_t)nB * DIM, nB,
                             g_sf[p][1], g_sf[q][1], g_sh[q][1], b2, nullptr, nullptr);
    } else {                        // s2' <- clip(.5 s2 + .5 (s1 @ W3^T + top + b4))
        const int nB = (bid - 96) * 128;
        gemm_unit<128, false>(dsm, 64, g_sh[p][1], gW3 + (size_t)nB * DIM,
                              g_sh[p][1], gW3 + (size_t)nB * DIM, nB,
                              g_sf[p][2], g_sf[q][2], g_sh[q][2], b4, g_top, nullptr);
    }
}

__global__ void __launch_bounds__(512, 1) top_kernel()
{
    extern __shared__ char dsm[];
    const int nB = blockIdx.x * 128;
    gemm_unit<128, true>(dsm, 64, g_s3h, gW4 + (size_t)nB * DIM,
                         g_s3h, gW4 + (size_t)nB * DIM, nB,
                         nullptr, nullptr, nullptr, nullptr, nullptr, g_top);
}

// -------- setup / teardown --------
__global__ void wconv_kernel(const float* __restrict__ w0, const float* __restrict__ w1,
                             const float* __restrict__ w2, const float* __restrict__ w3,
                             const float* __restrict__ w4)
{
    const float* src;
    __half* dst;
    switch (blockIdx.y) {
        case 0: src = w0; dst = gW0; break;
        case 1: src = w1; dst = gW1; break;
        case 2: src = w2; dst = gW2; break;
        case 3: src = w3; dst = gW3; break;
        default: src = w4; dst = gW4; break;
    }
    size_t i = ((size_t)blockIdx.x * blockDim.x + threadIdx.x) * 4;
    float4 v = *(const float4*)(src + i);
    __half2 h01 = __floats2half2_rn(v.x, v.y);
    __half2 h23 = __floats2half2_rn(v.z, v.w);
    *(__half2*)(dst + i)     = h01;
    *(__half2*)(dst + i + 2) = h23;
}

__global__ void init_kernel(const float* __restrict__ s0, const float* __restrict__ s1,
                            const float* __restrict__ s2, const float* __restrict__ s3)
{
    int i = blockIdx.x * blockDim.x + threadIdx.x;
    float v0 = s0[i], v1 = s1[i], v2 = s2[i];
    g_sf[0][0][i] = v0; g_sh[0][0][i] = __float2half_rn(v0);
    g_sf[0][1][i] = v1; g_sh[0][1][i] = __float2half_rn(v1);
    g_sf[0][2][i] = v2; g_sh[0][2][i] = __float2half_rn(v2);
    g_s3h[i] = __float2half_rn(s3[i]);
}

__global__ void out_kernel(float* __restrict__ out)
{
    int i = blockIdx.x * blockDim.x + threadIdx.x;
    out[i]          = g_sf[0][0][i];
    out[BD + i]     = g_sf[0][1][i];
    out[2 * BD + i] = g_sf[0][2][i];
}

extern "C" void kernel_launch(void* const* d_in, const int* in_sizes, int n_in,
                              void* d_out, int out_size)
{
    const float* s0 = (const float*)d_in[0];
    const float* s1 = (const float*)d_in[1];
    const float* s2 = (const float*)d_in[2];
    const float* s3 = (const float*)d_in[3];
    const float* W0 = (const float*)d_in[4];
    const float* b0 = (const float*)d_in[5];
    const float* W1 = (const float*)d_in[6];
    const float* W2 = (const float*)d_in[7];
    const float* b2 = (const float*)d_in[8];
    const float* W3 = (const float*)d_in[9];
    const float* W4 = (const float*)d_in[10];
    const float* b4 = (const float*)d_in[11];

    static_assert(SMEM_BYTES <= 227 * 1024, "smem budget");
    cudaFuncSetAttribute(step_kernel, cudaFuncAttributeMaxDynamicSharedMemorySize, SMEM_BYTES);
    cudaFuncSetAttribute(top_kernel,  cudaFuncAttributeMaxDynamicSharedMemorySize, SMEM_BYTES);

    wconv_kernel<<<dim3(DIM * DIM / 4 / 256, 5), 256>>>(W0, W1, W2, W3, W4);
    init_kernel<<<BD / 256, 256>>>(s0, s1, s2, s3);

    top_kernel<<<32, 512, SMEM_BYTES>>>();

    for (int t = 0; t < NSTEPS; t++)
        step_kernel<<<128, 512, SMEM_BYTES>>>(t & 1, b0, b2, b4);

    out_kernel<<<BD / 256, 256>>>((float*)d_out);
}